// round 1
// baseline (speedup 1.0000x reference)
#include <cuda_runtime.h>
#include <cuda_bf16.h>
#include <cstdint>

// Problem constants (fixed by the reference)
#define NN 50000
#define EE 600000
#define DD 128
#define HH 32

// ---------------------------------------------------------------------------
// Scratch (device globals; allocation is forbidden)
// ---------------------------------------------------------------------------
__device__ float4 g_xw4[NN * (DD / 4)];   // xw = x @ W_gcn, [N,128] as float4
__device__ float4 g_agg4[NN * (DD / 4)];  // scatter-add accumulator
__device__ float  g_dinv[NN];             // deg -> d^{-1/2} (in place)

// 16B vector reduction, no return value (REDG path, sm_90+)
__device__ __forceinline__ void red_add_f32x4(float4* addr, float4 v) {
    asm volatile("red.global.add.v4.f32 [%0], {%1, %2, %3, %4};"
                 :: "l"(addr), "f"(v.x), "f"(v.y), "f"(v.z), "f"(v.w)
                 : "memory");
}

// ---------------------------------------------------------------------------
// K1: init agg = 0, deg = 1 (self loop)
// ---------------------------------------------------------------------------
__global__ void k_init() {
    int i = blockIdx.x * blockDim.x + threadIdx.x;
    if (i < NN * (DD / 4)) g_agg4[i] = make_float4(0.f, 0.f, 0.f, 0.f);
    if (i < NN)            g_dinv[i] = 1.0f;   // holds degree first
}

// ---------------------------------------------------------------------------
// K2: degree via float atomics (exact: integer counts << 2^24)
// ---------------------------------------------------------------------------
__global__ void k_deg(const int* __restrict__ ei) {
    int i = blockIdx.x * blockDim.x + threadIdx.x;
    if (i >= EE) return;
    int col = __ldg(&ei[EE + i]);
    atomicAdd(&g_dinv[col], 1.0f);
}

// ---------------------------------------------------------------------------
// K3: deg -> rsqrt(deg)  (deg >= 1 always, no zero branch needed)
// ---------------------------------------------------------------------------
__global__ void k_dinv() {
    int i = blockIdx.x * blockDim.x + threadIdx.x;
    if (i >= NN) return;
    g_dinv[i] = rsqrtf(g_dinv[i]);
}

// ---------------------------------------------------------------------------
// K4: xw = x @ W   (M=50000, N=K=128), fp32 smem-tiled GEMM
//     256 threads; block tile 64 rows x 128 cols; thread micro-tile 8x4
// ---------------------------------------------------------------------------
__global__ __launch_bounds__(256) void k_gemm(const float* __restrict__ x,
                                              const float* __restrict__ W) {
    __shared__ float xs[64][32];
    __shared__ float ws[32][128];

    const int row0 = blockIdx.x * 64;
    const int tid  = threadIdx.x;
    const int tx   = tid & 31;   // col group: cols tx*4 .. tx*4+3
    const int ty   = tid >> 5;   // row group: rows ty*8 .. ty*8+7

    float acc[8][4];
    #pragma unroll
    for (int i = 0; i < 8; i++)
        #pragma unroll
        for (int j = 0; j < 4; j++) acc[i][j] = 0.f;

    for (int kk = 0; kk < DD; kk += 32) {
        // load x tile: 64 x 32
        #pragma unroll
        for (int p = 0; p < 8; p++) {
            int r = p * 8 + ty;
            int g = row0 + r;
            xs[r][tx] = (g < NN) ? __ldg(&x[g * DD + kk + tx]) : 0.f;
        }
        // load W tile: 32 x 128
        #pragma unroll
        for (int p = 0; p < 16; p++) {
            int i = p * 256 + tid;
            int k = i >> 7, c = i & 127;
            ws[k][c] = __ldg(&W[(kk + k) * DD + c]);
        }
        __syncthreads();

        #pragma unroll 8
        for (int k = 0; k < 32; k++) {
            float4 bv = *reinterpret_cast<const float4*>(&ws[k][tx * 4]);
            #pragma unroll
            for (int i = 0; i < 8; i++) {
                float a = xs[ty * 8 + i][k];   // broadcast within warp
                acc[i][0] = fmaf(a, bv.x, acc[i][0]);
                acc[i][1] = fmaf(a, bv.y, acc[i][1]);
                acc[i][2] = fmaf(a, bv.z, acc[i][2]);
                acc[i][3] = fmaf(a, bv.w, acc[i][3]);
            }
        }
        __syncthreads();
    }

    float* xw = reinterpret_cast<float*>(g_xw4);
    #pragma unroll
    for (int i = 0; i < 8; i++) {
        int g = row0 + ty * 8 + i;
        if (g < NN) {
            float4 v = make_float4(acc[i][0], acc[i][1], acc[i][2], acc[i][3]);
            *reinterpret_cast<float4*>(&xw[g * DD + tx * 4]) = v;
        }
    }
}

// ---------------------------------------------------------------------------
// K5: edge scatter — one warp per edge; vector red into agg[col]
// ---------------------------------------------------------------------------
__global__ __launch_bounds__(256) void k_edge(const int* __restrict__ ei) {
    int w    = (blockIdx.x * blockDim.x + threadIdx.x) >> 5;
    int lane = threadIdx.x & 31;
    if (w >= EE) return;
    int row = __ldg(&ei[w]);
    int col = __ldg(&ei[EE + w]);
    float norm = g_dinv[row] * g_dinv[col];
    float4 v = g_xw4[row * 32 + lane];
    v.x *= norm; v.y *= norm; v.z *= norm; v.w *= norm;
    red_add_f32x4(&g_agg4[col * 32 + lane], v);
}

// ---------------------------------------------------------------------------
// K6: fused epilogue + MLP head — one warp per node
//     h = relu(agg + xw*dinv^2 + b_gcn) + x; then 128->32->32->1 MLP
// ---------------------------------------------------------------------------
__global__ __launch_bounds__(256) void k_final(const float* __restrict__ x,
                                               const float* __restrict__ b_gcn,
                                               const float* __restrict__ w1,
                                               const float* __restrict__ b1,
                                               const float* __restrict__ w2,
                                               const float* __restrict__ b2,
                                               const float* __restrict__ w3,
                                               const float* __restrict__ b3,
                                               float* __restrict__ out) {
    int n    = (blockIdx.x * blockDim.x + threadIdx.x) >> 5;
    int lane = threadIdx.x & 31;
    if (n >= NN) return;

    float d  = g_dinv[n];
    float d2 = d * d;

    float4 av = g_agg4[n * 32 + lane];
    float4 wv = g_xw4[n * 32 + lane];
    float4 xv = reinterpret_cast<const float4*>(x)[n * 32 + lane];
    float4 bg = __ldg(&reinterpret_cast<const float4*>(b_gcn)[lane]);

    // h[k] for k = lane*4 + q
    float h0 = fmaxf(fmaf(wv.x, d2, av.x) + bg.x, 0.f) + xv.x;
    float h1 = fmaxf(fmaf(wv.y, d2, av.y) + bg.y, 0.f) + xv.y;
    float h2 = fmaxf(fmaf(wv.z, d2, av.z) + bg.z, 0.f) + xv.z;
    float h3 = fmaxf(fmaf(wv.w, d2, av.w) + bg.w, 0.f) + xv.w;

    // layer 1: [128] -> [32]; lane j accumulates h1[j]
    float a1 = __ldg(&b1[lane]);
    #pragma unroll
    for (int s = 0; s < 32; s++) {
        float t0 = __shfl_sync(0xFFFFFFFFu, h0, s);
        float t1 = __shfl_sync(0xFFFFFFFFu, h1, s);
        float t2 = __shfl_sync(0xFFFFFFFFu, h2, s);
        float t3 = __shfl_sync(0xFFFFFFFFu, h3, s);
        int k = s * 4;
        a1 = fmaf(t0, __ldg(&w1[(k + 0) * HH + lane]), a1);
        a1 = fmaf(t1, __ldg(&w1[(k + 1) * HH + lane]), a1);
        a1 = fmaf(t2, __ldg(&w1[(k + 2) * HH + lane]), a1);
        a1 = fmaf(t3, __ldg(&w1[(k + 3) * HH + lane]), a1);
    }
    a1 = fmaxf(a1, 0.f);

    // layer 2: [32] -> [32]
    float a2 = __ldg(&b2[lane]);
    #pragma unroll
    for (int s = 0; s < 32; s++) {
        float t = __shfl_sync(0xFFFFFFFFu, a1, s);
        a2 = fmaf(t, __ldg(&w2[s * HH + lane]), a2);
    }
    a2 = fmaxf(a2, 0.f);

    // layer 3: [32] -> [1], warp reduce
    float p = a2 * __ldg(&w3[lane]);
    #pragma unroll
    for (int off = 16; off > 0; off >>= 1)
        p += __shfl_xor_sync(0xFFFFFFFFu, p, off);

    if (lane == 0) out[n] = p + __ldg(&b3[0]);
}

// ---------------------------------------------------------------------------
// launch
// ---------------------------------------------------------------------------
extern "C" void kernel_launch(void* const* d_in, const int* in_sizes, int n_in,
                              void* d_out, int out_size) {
    const float* x     = (const float*)d_in[0];
    const int*   ei    = (const int*)  d_in[1];
    const float* W_gcn = (const float*)d_in[2];
    const float* b_gcn = (const float*)d_in[3];
    const float* w1    = (const float*)d_in[4];
    const float* b1    = (const float*)d_in[5];
    const float* w2    = (const float*)d_in[6];
    const float* b2    = (const float*)d_in[7];
    const float* w3    = (const float*)d_in[8];
    const float* b3    = (const float*)d_in[9];
    float* out = (float*)d_out;

    k_init<<<(NN * 32 + 255) / 256, 256>>>();
    k_deg<<<(EE + 255) / 256, 256>>>(ei);
    k_dinv<<<(NN + 255) / 256, 256>>>();
    k_gemm<<<(NN + 63) / 64, 256>>>(x, W_gcn);
    k_edge<<<(EE * 32 + 255) / 256, 256>>>(ei);
    k_final<<<(NN * 32 + 255) / 256, 256>>>(x, b_gcn, w1, b1, w2, b2, w3, b3, out);
}

// round 2
// speedup vs baseline: 1.0895x; 1.0895x over previous
#include <cuda_runtime.h>
#include <cuda_bf16.h>
#include <cstdint>

// Problem constants (fixed by the reference)
#define NN 50000
#define EE 600000
#define DD 128
#define HH 32

// ---------------------------------------------------------------------------
// Scratch (device globals; allocation is forbidden)
// ---------------------------------------------------------------------------
__device__ float4 g_xw4[NN * (DD / 4)];   // xw = x @ W_gcn, [N,128] as float4
__device__ float  g_dinv[NN];             // d^{-1/2} (includes self loop)
__device__ int    g_deg[NN];              // in-degree (edges only)
__device__ int    g_rowstart[NN + 1];     // CSR offsets (by target col)
__device__ int    g_cursor[NN];           // scatter cursors
__device__ int    g_srow[EE];             // source rows sorted by target col

// ---------------------------------------------------------------------------
// K0: zero degree counters
// ---------------------------------------------------------------------------
__global__ void k_init0() {
    int i = blockIdx.x * blockDim.x + threadIdx.x;
    if (i < NN) g_deg[i] = 0;
}

// ---------------------------------------------------------------------------
// K1: in-degree histogram (int atomics)
// ---------------------------------------------------------------------------
__global__ void k_count(const int* __restrict__ ei) {
    int i = blockIdx.x * blockDim.x + threadIdx.x;
    if (i >= EE) return;
    atomicAdd(&g_deg[__ldg(&ei[EE + i])], 1);
}

// ---------------------------------------------------------------------------
// K2: single-block exclusive scan over 50000 counts; also cursor + dinv
// ---------------------------------------------------------------------------
__global__ __launch_bounds__(1024) void k_scan() {
    __shared__ int wsum[32];
    __shared__ int s_carry;
    const int tid  = threadIdx.x;
    const int lane = tid & 31;
    const int w    = tid >> 5;
    if (tid == 0) s_carry = 0;
    __syncthreads();

    for (int base = 0; base < NN; base += 1024) {
        int i = base + tid;
        int v = (i < NN) ? g_deg[i] : 0;
        // inclusive warp scan
        int incl = v;
        #pragma unroll
        for (int d = 1; d < 32; d <<= 1) {
            int t = __shfl_up_sync(0xFFFFFFFFu, incl, d);
            if (lane >= d) incl += t;
        }
        if (lane == 31) wsum[w] = incl;
        __syncthreads();
        if (w == 0) {
            int s = wsum[lane];
            #pragma unroll
            for (int d = 1; d < 32; d <<= 1) {
                int t = __shfl_up_sync(0xFFFFFFFFu, s, d);
                if (lane >= d) s += t;
            }
            wsum[lane] = s;
        }
        __syncthreads();
        int offs = (w > 0) ? wsum[w - 1] : 0;
        int excl = s_carry + offs + incl - v;
        if (i < NN) {
            g_rowstart[i] = excl;
            g_cursor[i]   = excl;
            g_dinv[i]     = rsqrtf((float)(v + 1));  // +1 self loop
        }
        __syncthreads();
        if (tid == 0) s_carry += wsum[31];
        __syncthreads();
    }
    if (tid == 0) g_rowstart[NN] = EE;
}

// ---------------------------------------------------------------------------
// K3: bucket-scatter edges by target col
// ---------------------------------------------------------------------------
__global__ void k_scatter(const int* __restrict__ ei) {
    int i = blockIdx.x * blockDim.x + threadIdx.x;
    if (i >= EE) return;
    int row = __ldg(&ei[i]);
    int col = __ldg(&ei[EE + i]);
    int pos = atomicAdd(&g_cursor[col], 1);
    g_srow[pos] = row;
}

// ---------------------------------------------------------------------------
// K4: xw = x @ W   (M=50000, N=K=128), fp32 smem-tiled GEMM (unchanged)
// ---------------------------------------------------------------------------
__global__ __launch_bounds__(256) void k_gemm(const float* __restrict__ x,
                                              const float* __restrict__ W) {
    __shared__ float xs[64][32];
    __shared__ float ws[32][128];

    const int row0 = blockIdx.x * 64;
    const int tid  = threadIdx.x;
    const int tx   = tid & 31;
    const int ty   = tid >> 5;

    float acc[8][4];
    #pragma unroll
    for (int i = 0; i < 8; i++)
        #pragma unroll
        for (int j = 0; j < 4; j++) acc[i][j] = 0.f;

    for (int kk = 0; kk < DD; kk += 32) {
        #pragma unroll
        for (int p = 0; p < 8; p++) {
            int r = p * 8 + ty;
            int g = row0 + r;
            xs[r][tx] = (g < NN) ? __ldg(&x[g * DD + kk + tx]) : 0.f;
        }
        #pragma unroll
        for (int p = 0; p < 16; p++) {
            int i = p * 256 + tid;
            int k = i >> 7, c = i & 127;
            ws[k][c] = __ldg(&W[(kk + k) * DD + c]);
        }
        __syncthreads();

        #pragma unroll 8
        for (int k = 0; k < 32; k++) {
            float4 bv = *reinterpret_cast<const float4*>(&ws[k][tx * 4]);
            #pragma unroll
            for (int i = 0; i < 8; i++) {
                float a = xs[ty * 8 + i][k];
                acc[i][0] = fmaf(a, bv.x, acc[i][0]);
                acc[i][1] = fmaf(a, bv.y, acc[i][1]);
                acc[i][2] = fmaf(a, bv.z, acc[i][2]);
                acc[i][3] = fmaf(a, bv.w, acc[i][3]);
            }
        }
        __syncthreads();
    }

    float* xw = reinterpret_cast<float*>(g_xw4);
    #pragma unroll
    for (int i = 0; i < 8; i++) {
        int g = row0 + ty * 8 + i;
        if (g < NN) {
            float4 v = make_float4(acc[i][0], acc[i][1], acc[i][2], acc[i][3]);
            *reinterpret_cast<float4*>(&xw[g * DD + tx * 4]) = v;
        }
    }
}

// ---------------------------------------------------------------------------
// K5: fused CSR gather-aggregate + epilogue + MLP — one warp per node
//     agg = dinv[n] * ( sum_in dinv[row]*xw[row] + dinv[n]*xw[n] )
//     h = relu(agg + b_gcn) + x;  out = mlp(h)
// ---------------------------------------------------------------------------
__global__ __launch_bounds__(256) void k_aggmlp(const float* __restrict__ x,
                                                const float* __restrict__ b_gcn,
                                                const float* __restrict__ w1,
                                                const float* __restrict__ b1,
                                                const float* __restrict__ w2,
                                                const float* __restrict__ b2,
                                                const float* __restrict__ w3,
                                                const float* __restrict__ b3,
                                                float* __restrict__ out) {
    int n    = (blockIdx.x * blockDim.x + threadIdx.x) >> 5;
    int lane = threadIdx.x & 31;
    if (n >= NN) return;

    int e0 = __ldg(&g_rowstart[n]);
    int e1 = __ldg(&g_rowstart[n + 1]);

    float4 acc0 = make_float4(0.f, 0.f, 0.f, 0.f);
    float4 acc1 = make_float4(0.f, 0.f, 0.f, 0.f);

    int e = e0;
    for (; e + 1 < e1; e += 2) {
        int ra = g_srow[e];
        int rb = g_srow[e + 1];
        float sa = g_dinv[ra];
        float sb = g_dinv[rb];
        float4 va = g_xw4[ra * 32 + lane];
        float4 vb = g_xw4[rb * 32 + lane];
        acc0.x = fmaf(sa, va.x, acc0.x); acc0.y = fmaf(sa, va.y, acc0.y);
        acc0.z = fmaf(sa, va.z, acc0.z); acc0.w = fmaf(sa, va.w, acc0.w);
        acc1.x = fmaf(sb, vb.x, acc1.x); acc1.y = fmaf(sb, vb.y, acc1.y);
        acc1.z = fmaf(sb, vb.z, acc1.z); acc1.w = fmaf(sb, vb.w, acc1.w);
    }
    if (e < e1) {
        int ra = g_srow[e];
        float sa = g_dinv[ra];
        float4 va = g_xw4[ra * 32 + lane];
        acc0.x = fmaf(sa, va.x, acc0.x); acc0.y = fmaf(sa, va.y, acc0.y);
        acc0.z = fmaf(sa, va.z, acc0.z); acc0.w = fmaf(sa, va.w, acc0.w);
    }
    acc0.x += acc1.x; acc0.y += acc1.y; acc0.z += acc1.z; acc0.w += acc1.w;

    float d = g_dinv[n];
    float4 wv = g_xw4[n * 32 + lane];
    float4 xv = reinterpret_cast<const float4*>(x)[n * 32 + lane];
    float4 bg = __ldg(&reinterpret_cast<const float4*>(b_gcn)[lane]);

    // agg = d*(acc + d*wv); h = relu(agg + bg) + x
    float h0 = fmaxf(fmaf(d, fmaf(d, wv.x, acc0.x), 0.f) + bg.x, 0.f) + xv.x;
    float h1 = fmaxf(fmaf(d, fmaf(d, wv.y, acc0.y), 0.f) + bg.y, 0.f) + xv.y;
    float h2 = fmaxf(fmaf(d, fmaf(d, wv.z, acc0.z), 0.f) + bg.z, 0.f) + xv.z;
    float h3 = fmaxf(fmaf(d, fmaf(d, wv.w, acc0.w), 0.f) + bg.w, 0.f) + xv.w;

    // layer 1: [128] -> [32]; lane j accumulates h1[j]
    float a1 = __ldg(&b1[lane]);
    #pragma unroll
    for (int s = 0; s < 32; s++) {
        float t0 = __shfl_sync(0xFFFFFFFFu, h0, s);
        float t1 = __shfl_sync(0xFFFFFFFFu, h1, s);
        float t2 = __shfl_sync(0xFFFFFFFFu, h2, s);
        float t3 = __shfl_sync(0xFFFFFFFFu, h3, s);
        int k = s * 4;
        a1 = fmaf(t0, __ldg(&w1[(k + 0) * HH + lane]), a1);
        a1 = fmaf(t1, __ldg(&w1[(k + 1) * HH + lane]), a1);
        a1 = fmaf(t2, __ldg(&w1[(k + 2) * HH + lane]), a1);
        a1 = fmaf(t3, __ldg(&w1[(k + 3) * HH + lane]), a1);
    }
    a1 = fmaxf(a1, 0.f);

    // layer 2: [32] -> [32]
    float a2 = __ldg(&b2[lane]);
    #pragma unroll
    for (int s = 0; s < 32; s++) {
        float t = __shfl_sync(0xFFFFFFFFu, a1, s);
        a2 = fmaf(t, __ldg(&w2[s * HH + lane]), a2);
    }
    a2 = fmaxf(a2, 0.f);

    // layer 3: [32] -> [1], warp reduce
    float p = a2 * __ldg(&w3[lane]);
    #pragma unroll
    for (int off = 16; off > 0; off >>= 1)
        p += __shfl_xor_sync(0xFFFFFFFFu, p, off);

    if (lane == 0) out[n] = p + __ldg(&b3[0]);
}

// ---------------------------------------------------------------------------
// launch
// ---------------------------------------------------------------------------
extern "C" void kernel_launch(void* const* d_in, const int* in_sizes, int n_in,
                              void* d_out, int out_size) {
    const float* x     = (const float*)d_in[0];
    const int*   ei    = (const int*)  d_in[1];
    const float* W_gcn = (const float*)d_in[2];
    const float* b_gcn = (const float*)d_in[3];
    const float* w1    = (const float*)d_in[4];
    const float* b1    = (const float*)d_in[5];
    const float* w2    = (const float*)d_in[6];
    const float* b2    = (const float*)d_in[7];
    const float* w3    = (const float*)d_in[8];
    const float* b3    = (const float*)d_in[9];
    float* out = (float*)d_out;

    k_init0  <<<(NN + 255) / 256, 256>>>();
    k_count  <<<(EE + 255) / 256, 256>>>(ei);
    k_scan   <<<1, 1024>>>();
    k_scatter<<<(EE + 255) / 256, 256>>>(ei);
    k_gemm   <<<(NN + 63) / 64, 256>>>(x, W_gcn);
    k_aggmlp <<<(NN * 32 + 255) / 256, 256>>>(x, b_gcn, w1, b1, w2, b2, w3, b3, out);
}

// round 4
// speedup vs baseline: 1.5640x; 1.4355x over previous
#include <cuda_runtime.h>
#include <cuda_bf16.h>
#include <cstdint>

#define NN 50000
#define EE 600000
#define DD 128
#define HH 32

// ---------------------------------------------------------------------------
// Scratch
// ---------------------------------------------------------------------------
__device__ float4 g_xw4[NN * (DD / 4)];   // xw = x @ W_gcn
__device__ float  g_dinv[NN];
__device__ int    g_deg[NN];
__device__ int    g_excl[NN];             // in-block exclusive prefix
__device__ int    g_bsum[256];            // per-block sums (196 used)
__device__ int    g_boff[256];            // scanned block offsets
__device__ int    g_rowstart[NN + 1];
__device__ int    g_cursor[NN];
__device__ int    g_srow[EE];

// ---------------------------------------------------------------------------
// K0: zero degree counters
// ---------------------------------------------------------------------------
__global__ void k_init0() {
    int i = blockIdx.x * blockDim.x + threadIdx.x;
    if (i < NN) g_deg[i] = 0;
}

// ---------------------------------------------------------------------------
// K1: in-degree histogram
// ---------------------------------------------------------------------------
__global__ void k_count(const int* __restrict__ ei) {
    int i = blockIdx.x * blockDim.x + threadIdx.x;
    if (i >= EE) return;
    atomicAdd(&g_deg[__ldg(&ei[EE + i])], 1);
}

// ---------------------------------------------------------------------------
// K2a: per-block scan (196 blocks x 256) + dinv
// ---------------------------------------------------------------------------
__global__ __launch_bounds__(256) void k_scan1() {
    __shared__ int wsum[8];
    const int tid  = threadIdx.x;
    const int lane = tid & 31;
    const int w    = tid >> 5;
    const int i    = blockIdx.x * 256 + tid;

    int v = (i < NN) ? g_deg[i] : 0;
    int incl = v;
    #pragma unroll
    for (int d = 1; d < 32; d <<= 1) {
        int t = __shfl_up_sync(0xFFFFFFFFu, incl, d);
        if (lane >= d) incl += t;
    }
    if (lane == 31) wsum[w] = incl;
    __syncthreads();
    if (w == 0 && lane < 8) {
        int s = wsum[lane];
        #pragma unroll
        for (int d = 1; d < 8; d <<= 1) {
            int t = __shfl_up_sync(0xFFu, s, d);
            if (lane >= d) s += t;
        }
        wsum[lane] = s;
    }
    __syncthreads();
    int offs = (w > 0) ? wsum[w - 1] : 0;
    if (i < NN) {
        g_excl[i] = offs + incl - v;
        g_dinv[i] = rsqrtf((float)(v + 1));
    }
    if (tid == 255) g_bsum[blockIdx.x] = wsum[7];
}

// ---------------------------------------------------------------------------
// K2b: scan the 196 block sums (1 block of 256)
// ---------------------------------------------------------------------------
__global__ __launch_bounds__(256) void k_scan2(int nblk) {
    __shared__ int wsum[8];
    const int tid  = threadIdx.x;
    const int lane = tid & 31;
    const int w    = tid >> 5;
    int v = (tid < nblk) ? g_bsum[tid] : 0;
    int incl = v;
    #pragma unroll
    for (int d = 1; d < 32; d <<= 1) {
        int t = __shfl_up_sync(0xFFFFFFFFu, incl, d);
        if (lane >= d) incl += t;
    }
    if (lane == 31) wsum[w] = incl;
    __syncthreads();
    if (w == 0 && lane < 8) {
        int s = wsum[lane];
        #pragma unroll
        for (int d = 1; d < 8; d <<= 1) {
            int t = __shfl_up_sync(0xFFu, s, d);
            if (lane >= d) s += t;
        }
        wsum[lane] = s;
    }
    __syncthreads();
    int offs = (w > 0) ? wsum[w - 1] : 0;
    g_boff[tid] = offs + incl - v;   // exclusive
}

// ---------------------------------------------------------------------------
// K2c: rowstart = excl + block offset; cursor copy
// ---------------------------------------------------------------------------
__global__ __launch_bounds__(256) void k_scan3() {
    int i = blockIdx.x * blockDim.x + threadIdx.x;
    if (i < NN) {
        int r = g_excl[i] + g_boff[i >> 8];
        g_rowstart[i] = r;
        g_cursor[i]   = r;
    }
    if (i == 0) g_rowstart[NN] = EE;
}

// ---------------------------------------------------------------------------
// K3: bucket-scatter edges by target col
// ---------------------------------------------------------------------------
__global__ void k_scatter(const int* __restrict__ ei) {
    int i = blockIdx.x * blockDim.x + threadIdx.x;
    if (i >= EE) return;
    int row = __ldg(&ei[i]);
    int col = __ldg(&ei[EE + i]);
    int pos = atomicAdd(&g_cursor[col], 1);
    g_srow[pos] = row;
}

// ---------------------------------------------------------------------------
// K4: xw = x @ W via mma.sync tf32 (m16n8k8), fp32 accumulate
//     Block: 128 threads (4 warps), 64 rows; full 128-col output per warp tile m16
// ---------------------------------------------------------------------------
__device__ __forceinline__ uint32_t f2tf32(float f) {
    uint32_t r;
    asm("cvt.rna.tf32.f32 %0, %1;" : "=r"(r) : "f"(f));
    return r;
}

#define XS_STRIDE 132
#define WS_STRIDE 136

__global__ __launch_bounds__(128) void k_gemm_mma(const float* __restrict__ x,
                                                  const float* __restrict__ W) {
    extern __shared__ float smem[];
    float* xs = smem;                       // [64][132]
    float* ws = smem + 64 * XS_STRIDE;      // [128][136]

    const int tid  = threadIdx.x;
    const int lane = tid & 31;
    const int warp = tid >> 5;
    const int row0 = blockIdx.x * 64;

    // Load W tile (128x128) -> tf32 bits in smem
    #pragma unroll
    for (int it = 0; it < 32; it++) {
        int idx = tid + it * 128;           // float4 index
        int k  = idx >> 5;
        int c4 = (idx & 31) * 4;
        float4 v = __ldg(reinterpret_cast<const float4*>(&W[k * DD + c4]));
        float* d = &ws[k * WS_STRIDE + c4];
        d[0] = __uint_as_float(f2tf32(v.x));
        d[1] = __uint_as_float(f2tf32(v.y));
        d[2] = __uint_as_float(f2tf32(v.z));
        d[3] = __uint_as_float(f2tf32(v.w));
    }
    // Load x tile (64x128) -> tf32 bits
    #pragma unroll
    for (int it = 0; it < 16; it++) {
        int idx = tid + it * 128;
        int r  = idx >> 5;
        int c4 = (idx & 31) * 4;
        int g  = row0 + r;
        float4 v = make_float4(0.f, 0.f, 0.f, 0.f);
        if (g < NN) v = __ldg(reinterpret_cast<const float4*>(&x[g * DD + c4]));
        float* d = &xs[r * XS_STRIDE + c4];
        d[0] = __uint_as_float(f2tf32(v.x));
        d[1] = __uint_as_float(f2tf32(v.y));
        d[2] = __uint_as_float(f2tf32(v.z));
        d[3] = __uint_as_float(f2tf32(v.w));
    }
    __syncthreads();

    const int g  = lane >> 2;   // 0..7
    const int tg = lane & 3;    // 0..3
    const int wrow = warp * 16;

    float acc[16][4];
    #pragma unroll
    for (int nt = 0; nt < 16; nt++)
        #pragma unroll
        for (int q = 0; q < 4; q++) acc[nt][q] = 0.f;

    #pragma unroll
    for (int kk = 0; kk < DD; kk += 8) {
        uint32_t a0 = __float_as_uint(xs[(wrow + g    ) * XS_STRIDE + kk + tg    ]);
        uint32_t a1 = __float_as_uint(xs[(wrow + g + 8) * XS_STRIDE + kk + tg    ]);
        uint32_t a2 = __float_as_uint(xs[(wrow + g    ) * XS_STRIDE + kk + tg + 4]);
        uint32_t a3 = __float_as_uint(xs[(wrow + g + 8) * XS_STRIDE + kk + tg + 4]);
        #pragma unroll
        for (int nt = 0; nt < 16; nt++) {
            uint32_t b0 = __float_as_uint(ws[(kk + tg    ) * WS_STRIDE + nt * 8 + g]);
            uint32_t b1 = __float_as_uint(ws[(kk + tg + 4) * WS_STRIDE + nt * 8 + g]);
            asm volatile(
                "mma.sync.aligned.m16n8k8.row.col.f32.tf32.tf32.f32 "
                "{%0,%1,%2,%3}, {%4,%5,%6,%7}, {%8,%9}, {%0,%1,%2,%3};"
                : "+f"(acc[nt][0]), "+f"(acc[nt][1]), "+f"(acc[nt][2]), "+f"(acc[nt][3])
                : "r"(a0), "r"(a1), "r"(a2), "r"(a3), "r"(b0), "r"(b1));
        }
    }

    // Epilogue: c0/c1 -> (row wrow+g, col nt*8+2tg, +1); c2/c3 -> row+8
    float* xw = reinterpret_cast<float*>(g_xw4);
    int r_lo = row0 + wrow + g;
    int r_hi = r_lo + 8;
    #pragma unroll
    for (int nt = 0; nt < 16; nt++) {
        int col = nt * 8 + 2 * tg;
        if (r_lo < NN) {
            float2 v = make_float2(acc[nt][0], acc[nt][1]);
            *reinterpret_cast<float2*>(&xw[r_lo * DD + col]) = v;
        }
        if (r_hi < NN) {
            float2 v = make_float2(acc[nt][2], acc[nt][3]);
            *reinterpret_cast<float2*>(&xw[r_hi * DD + col]) = v;
        }
    }
}

// ---------------------------------------------------------------------------
// K5: fused CSR gather + epilogue + MLP — one warp per node
// ---------------------------------------------------------------------------
__global__ __launch_bounds__(256) void k_aggmlp(const float* __restrict__ x,
                                                const float* __restrict__ b_gcn,
                                                const float* __restrict__ w1,
                                                const float* __restrict__ b1,
                                                const float* __restrict__ w2,
                                                const float* __restrict__ b2,
                                                const float* __restrict__ w3,
                                                const float* __restrict__ b3,
                                                float* __restrict__ out) {
    int n    = (blockIdx.x * blockDim.x + threadIdx.x) >> 5;
    int lane = threadIdx.x & 31;
    if (n >= NN) return;

    int e0  = __ldg(&g_rowstart[n]);
    int e1  = __ldg(&g_rowstart[n + 1]);
    int cnt = e1 - e0;

    // Preload up to 32 (srow, dinv) pairs into lanes; broadcast via shfl.
    int   sr = 0;
    float sd = 0.f;
    if (lane < cnt) {
        sr = __ldg(&g_srow[e0 + lane]);
        sd = g_dinv[sr];
    }

    float4 acc0 = make_float4(0.f, 0.f, 0.f, 0.f);
    float4 acc1 = make_float4(0.f, 0.f, 0.f, 0.f);

    int m = cnt < 32 ? cnt : 32;
    int j = 0;
    for (; j + 1 < m; j += 2) {
        int   ra = __shfl_sync(0xFFFFFFFFu, sr, j);
        float sa = __shfl_sync(0xFFFFFFFFu, sd, j);
        int   rb = __shfl_sync(0xFFFFFFFFu, sr, j + 1);
        float sb = __shfl_sync(0xFFFFFFFFu, sd, j + 1);
        float4 va = g_xw4[ra * 32 + lane];
        float4 vb = g_xw4[rb * 32 + lane];
        acc0.x = fmaf(sa, va.x, acc0.x); acc0.y = fmaf(sa, va.y, acc0.y);
        acc0.z = fmaf(sa, va.z, acc0.z); acc0.w = fmaf(sa, va.w, acc0.w);
        acc1.x = fmaf(sb, vb.x, acc1.x); acc1.y = fmaf(sb, vb.y, acc1.y);
        acc1.z = fmaf(sb, vb.z, acc1.z); acc1.w = fmaf(sb, vb.w, acc1.w);
    }
    if (j < m) {
        int   ra = __shfl_sync(0xFFFFFFFFu, sr, j);
        float sa = __shfl_sync(0xFFFFFFFFu, sd, j);
        float4 va = g_xw4[ra * 32 + lane];
        acc0.x = fmaf(sa, va.x, acc0.x); acc0.y = fmaf(sa, va.y, acc0.y);
        acc0.z = fmaf(sa, va.z, acc0.z); acc0.w = fmaf(sa, va.w, acc0.w);
    }
    // Rare tail (deg > 32)
    for (int e = e0 + 32; e < e1; e++) {
        int ra = g_srow[e];
        float sa = g_dinv[ra];
        float4 va = g_xw4[ra * 32 + lane];
        acc0.x = fmaf(sa, va.x, acc0.x); acc0.y = fmaf(sa, va.y, acc0.y);
        acc0.z = fmaf(sa, va.z, acc0.z); acc0.w = fmaf(sa, va.w, acc0.w);
    }
    acc0.x += acc1.x; acc0.y += acc1.y; acc0.z += acc1.z; acc0.w += acc1.w;

    float d = g_dinv[n];
    float4 wv = g_xw4[n * 32 + lane];
    float4 xv = reinterpret_cast<const float4*>(x)[n * 32 + lane];
    float4 bg = __ldg(&reinterpret_cast<const float4*>(b_gcn)[lane]);

    float h0 = fmaxf(d * fmaf(d, wv.x, acc0.x) + bg.x, 0.f) + xv.x;
    float h1 = fmaxf(d * fmaf(d, wv.y, acc0.y) + bg.y, 0.f) + xv.y;
    float h2 = fmaxf(d * fmaf(d, wv.z, acc0.z) + bg.z, 0.f) + xv.z;
    float h3 = fmaxf(d * fmaf(d, wv.w, acc0.w) + bg.w, 0.f) + xv.w;

    // layer 1: [128] -> [32]
    float a1 = __ldg(&b1[lane]);
    #pragma unroll
    for (int s = 0; s < 32; s++) {
        float t0 = __shfl_sync(0xFFFFFFFFu, h0, s);
        float t1 = __shfl_sync(0xFFFFFFFFu, h1, s);
        float t2 = __shfl_sync(0xFFFFFFFFu, h2, s);
        float t3 = __shfl_sync(0xFFFFFFFFu, h3, s);
        int k = s * 4;
        a1 = fmaf(t0, __ldg(&w1[(k + 0) * HH + lane]), a1);
        a1 = fmaf(t1, __ldg(&w1[(k + 1) * HH + lane]), a1);
        a1 = fmaf(t2, __ldg(&w1[(k + 2) * HH + lane]), a1);
        a1 = fmaf(t3, __ldg(&w1[(k + 3) * HH + lane]), a1);
    }
    a1 = fmaxf(a1, 0.f);

    // layer 2: [32] -> [32]
    float a2 = __ldg(&b2[lane]);
    #pragma unroll
    for (int s = 0; s < 32; s++) {
        float t = __shfl_sync(0xFFFFFFFFu, a1, s);
        a2 = fmaf(t, __ldg(&w2[s * HH + lane]), a2);
    }
    a2 = fmaxf(a2, 0.f);

    // layer 3: [32] -> [1]
    float p = a2 * __ldg(&w3[lane]);
    #pragma unroll
    for (int off = 16; off > 0; off >>= 1)
        p += __shfl_xor_sync(0xFFFFFFFFu, p, off);

    if (lane == 0) out[n] = p + __ldg(&b3[0]);
}

// ---------------------------------------------------------------------------
// launch
// ---------------------------------------------------------------------------
extern "C" void kernel_launch(void* const* d_in, const int* in_sizes, int n_in,
                              void* d_out, int out_size) {
    const float* x     = (const float*)d_in[0];
    const int*   ei    = (const int*)  d_in[1];
    const float* W_gcn = (const float*)d_in[2];
    const float* b_gcn = (const float*)d_in[3];
    const float* w1    = (const float*)d_in[4];
    const float* b1    = (const float*)d_in[5];
    const float* w2    = (const float*)d_in[6];
    const float* b2    = (const float*)d_in[7];
    const float* w3    = (const float*)d_in[8];
    const float* b3    = (const float*)d_in[9];
    float* out = (float*)d_out;

    const int smem_bytes = (64 * XS_STRIDE + 128 * WS_STRIDE) * sizeof(float);
    static bool attr_set = false;
    if (!attr_set) {
        cudaFuncSetAttribute(k_gemm_mma, cudaFuncAttributeMaxDynamicSharedMemorySize,
                             smem_bytes);
        attr_set = true;
    }

    const int nblk = (NN + 255) / 256;  // 196

    k_gemm_mma<<<(NN + 63) / 64, 128, smem_bytes>>>(x, W_gcn);
    k_init0  <<<nblk, 256>>>();
    k_count  <<<(EE + 255) / 256, 256>>>(ei);
    k_scan1  <<<nblk, 256>>>();
    k_scan2  <<<1, 256>>>(nblk);
    k_scan3  <<<nblk, 256>>>();
    k_scatter<<<(EE + 255) / 256, 256>>>(ei);
    k_aggmlp <<<(NN * 32 + 255) / 256, 256>>>(x, b_gcn, w1, b1, w2, b2, w3, b3, out);
}

// round 5
// speedup vs baseline: 1.6818x; 1.0753x over previous
#include <cuda_runtime.h>
#include <cuda_bf16.h>
#include <cuda_fp16.h>
#include <cstdint>

#define NN 50000
#define EE 600000
#define DD 128
#define HH 32

// ---------------------------------------------------------------------------
// Scratch
// ---------------------------------------------------------------------------
__device__ float4  g_xw4[NN * (DD / 4)];  // xw = x @ W_gcn (fp32, self term)
__device__ __half2 g_xwh2[NN * (DD / 2)]; // dinv[row]*xw[row] in fp16 (gather)
__device__ float   g_dinv[NN];
__device__ int     g_deg[NN];
__device__ int     g_excl[NN];
__device__ int     g_bsum[256];
__device__ int     g_boff[256];
__device__ int     g_rowstart[NN + 1];
__device__ int     g_cursor[NN];
__device__ int     g_srow[EE];

// ---------------------------------------------------------------------------
__global__ void k_init0() {
    int i = blockIdx.x * blockDim.x + threadIdx.x;
    if (i < NN) g_deg[i] = 0;
}

__global__ void k_count(const int* __restrict__ ei) {
    int i = blockIdx.x * blockDim.x + threadIdx.x;
    if (i >= EE) return;
    atomicAdd(&g_deg[__ldg(&ei[EE + i])], 1);
}

// K2a: per-block scan (196 blocks x 256) + dinv
__global__ __launch_bounds__(256) void k_scan1() {
    __shared__ int wsum[8];
    const int tid  = threadIdx.x;
    const int lane = tid & 31;
    const int w    = tid >> 5;
    const int i    = blockIdx.x * 256 + tid;

    int v = (i < NN) ? g_deg[i] : 0;
    int incl = v;
    #pragma unroll
    for (int d = 1; d < 32; d <<= 1) {
        int t = __shfl_up_sync(0xFFFFFFFFu, incl, d);
        if (lane >= d) incl += t;
    }
    if (lane == 31) wsum[w] = incl;
    __syncthreads();
    if (w == 0 && lane < 8) {
        int s = wsum[lane];
        #pragma unroll
        for (int d = 1; d < 8; d <<= 1) {
            int t = __shfl_up_sync(0xFFu, s, d);
            if (lane >= d) s += t;
        }
        wsum[lane] = s;
    }
    __syncthreads();
    int offs = (w > 0) ? wsum[w - 1] : 0;
    if (i < NN) {
        g_excl[i] = offs + incl - v;
        g_dinv[i] = rsqrtf((float)(v + 1));
    }
    if (tid == 255) g_bsum[blockIdx.x] = wsum[7];
}

__global__ __launch_bounds__(256) void k_scan2(int nblk) {
    __shared__ int wsum[8];
    const int tid  = threadIdx.x;
    const int lane = tid & 31;
    const int w    = tid >> 5;
    int v = (tid < nblk) ? g_bsum[tid] : 0;
    int incl = v;
    #pragma unroll
    for (int d = 1; d < 32; d <<= 1) {
        int t = __shfl_up_sync(0xFFFFFFFFu, incl, d);
        if (lane >= d) incl += t;
    }
    if (lane == 31) wsum[w] = incl;
    __syncthreads();
    if (w == 0 && lane < 8) {
        int s = wsum[lane];
        #pragma unroll
        for (int d = 1; d < 8; d <<= 1) {
            int t = __shfl_up_sync(0xFFu, s, d);
            if (lane >= d) s += t;
        }
        wsum[lane] = s;
    }
    __syncthreads();
    int offs = (w > 0) ? wsum[w - 1] : 0;
    g_boff[tid] = offs + incl - v;
}

__global__ __launch_bounds__(256) void k_scan3() {
    int i = blockIdx.x * blockDim.x + threadIdx.x;
    if (i < NN) {
        int r = g_excl[i] + g_boff[i >> 8];
        g_rowstart[i] = r;
        g_cursor[i]   = r;
    }
    if (i == 0) g_rowstart[NN] = EE;
}

__global__ void k_scatter(const int* __restrict__ ei) {
    int i = blockIdx.x * blockDim.x + threadIdx.x;
    if (i >= EE) return;
    int row = __ldg(&ei[i]);
    int col = __ldg(&ei[EE + i]);
    int pos = atomicAdd(&g_cursor[col], 1);
    g_srow[pos] = row;
}

// ---------------------------------------------------------------------------
// K4: xw = x @ W via mma.sync tf32 (unchanged from R4)
// ---------------------------------------------------------------------------
__device__ __forceinline__ uint32_t f2tf32(float f) {
    uint32_t r;
    asm("cvt.rna.tf32.f32 %0, %1;" : "=r"(r) : "f"(f));
    return r;
}

#define XS_STRIDE 132
#define WS_STRIDE 136

__global__ __launch_bounds__(128) void k_gemm_mma(const float* __restrict__ x,
                                                  const float* __restrict__ W) {
    extern __shared__ float smem[];
    float* xs = smem;                       // [64][132]
    float* ws = smem + 64 * XS_STRIDE;      // [128][136]

    const int tid  = threadIdx.x;
    const int lane = tid & 31;
    const int warp = tid >> 5;
    const int row0 = blockIdx.x * 64;

    #pragma unroll
    for (int it = 0; it < 32; it++) {
        int idx = tid + it * 128;
        int k  = idx >> 5;
        int c4 = (idx & 31) * 4;
        float4 v = __ldg(reinterpret_cast<const float4*>(&W[k * DD + c4]));
        float* d = &ws[k * WS_STRIDE + c4];
        d[0] = __uint_as_float(f2tf32(v.x));
        d[1] = __uint_as_float(f2tf32(v.y));
        d[2] = __uint_as_float(f2tf32(v.z));
        d[3] = __uint_as_float(f2tf32(v.w));
    }
    #pragma unroll
    for (int it = 0; it < 16; it++) {
        int idx = tid + it * 128;
        int r  = idx >> 5;
        int c4 = (idx & 31) * 4;
        int g  = row0 + r;
        float4 v = make_float4(0.f, 0.f, 0.f, 0.f);
        if (g < NN) v = __ldg(reinterpret_cast<const float4*>(&x[g * DD + c4]));
        float* d = &xs[r * XS_STRIDE + c4];
        d[0] = __uint_as_float(f2tf32(v.x));
        d[1] = __uint_as_float(f2tf32(v.y));
        d[2] = __uint_as_float(f2tf32(v.z));
        d[3] = __uint_as_float(f2tf32(v.w));
    }
    __syncthreads();

    const int g  = lane >> 2;
    const int tg = lane & 3;
    const int wrow = warp * 16;

    float acc[16][4];
    #pragma unroll
    for (int nt = 0; nt < 16; nt++)
        #pragma unroll
        for (int q = 0; q < 4; q++) acc[nt][q] = 0.f;

    #pragma unroll
    for (int kk = 0; kk < DD; kk += 8) {
        uint32_t a0 = __float_as_uint(xs[(wrow + g    ) * XS_STRIDE + kk + tg    ]);
        uint32_t a1 = __float_as_uint(xs[(wrow + g + 8) * XS_STRIDE + kk + tg    ]);
        uint32_t a2 = __float_as_uint(xs[(wrow + g    ) * XS_STRIDE + kk + tg + 4]);
        uint32_t a3 = __float_as_uint(xs[(wrow + g + 8) * XS_STRIDE + kk + tg + 4]);
        #pragma unroll
        for (int nt = 0; nt < 16; nt++) {
            uint32_t b0 = __float_as_uint(ws[(kk + tg    ) * WS_STRIDE + nt * 8 + g]);
            uint32_t b1 = __float_as_uint(ws[(kk + tg + 4) * WS_STRIDE + nt * 8 + g]);
            asm volatile(
                "mma.sync.aligned.m16n8k8.row.col.f32.tf32.tf32.f32 "
                "{%0,%1,%2,%3}, {%4,%5,%6,%7}, {%8,%9}, {%0,%1,%2,%3};"
                : "+f"(acc[nt][0]), "+f"(acc[nt][1]), "+f"(acc[nt][2]), "+f"(acc[nt][3])
                : "r"(a0), "r"(a1), "r"(a2), "r"(a3), "r"(b0), "r"(b1));
        }
    }

    float* xw = reinterpret_cast<float*>(g_xw4);
    int r_lo = row0 + wrow + g;
    int r_hi = r_lo + 8;
    #pragma unroll
    for (int nt = 0; nt < 16; nt++) {
        int col = nt * 8 + 2 * tg;
        if (r_lo < NN) {
            float2 v = make_float2(acc[nt][0], acc[nt][1]);
            *reinterpret_cast<float2*>(&xw[r_lo * DD + col]) = v;
        }
        if (r_hi < NN) {
            float2 v = make_float2(acc[nt][2], acc[nt][3]);
            *reinterpret_cast<float2*>(&xw[r_hi * DD + col]) = v;
        }
    }
}

// ---------------------------------------------------------------------------
// K4b: xws = fp16(dinv[row] * xw[row])  — premultiplied gather matrix
// ---------------------------------------------------------------------------
__global__ __launch_bounds__(256) void k_scale() {
    int idx = blockIdx.x * blockDim.x + threadIdx.x;   // over NN*32 float4s
    if (idx >= NN * 32) return;
    float d = g_dinv[idx >> 5];
    float4 v = g_xw4[idx];
    __half2 h0 = __floats2half2_rn(v.x * d, v.y * d);
    __half2 h1 = __floats2half2_rn(v.z * d, v.w * d);
    uint2 u;
    u.x = *reinterpret_cast<uint32_t*>(&h0);
    u.y = *reinterpret_cast<uint32_t*>(&h1);
    *reinterpret_cast<uint2*>(&g_xwh2[idx * 2]) = u;
}

// ---------------------------------------------------------------------------
// K5: fused CSR gather (fp16 rows, pure sum) + epilogue + MLP
// ---------------------------------------------------------------------------
__device__ __forceinline__ void acc_row(float4& a, int row, int lane) {
    uint2 u = __ldg(reinterpret_cast<const uint2*>(&g_xwh2[row * 64 + lane * 2]));
    float2 fa = __half22float2(*reinterpret_cast<__half2*>(&u.x));
    float2 fb = __half22float2(*reinterpret_cast<__half2*>(&u.y));
    a.x += fa.x; a.y += fa.y; a.z += fb.x; a.w += fb.y;
}

__global__ __launch_bounds__(256) void k_aggmlp(const float* __restrict__ x,
                                                const float* __restrict__ b_gcn,
                                                const float* __restrict__ w1,
                                                const float* __restrict__ b1,
                                                const float* __restrict__ w2,
                                                const float* __restrict__ b2,
                                                const float* __restrict__ w3,
                                                const float* __restrict__ b3,
                                                float* __restrict__ out) {
    int n    = (blockIdx.x * blockDim.x + threadIdx.x) >> 5;
    int lane = threadIdx.x & 31;
    if (n >= NN) return;

    int e0  = __ldg(&g_rowstart[n]);
    int e1  = __ldg(&g_rowstart[n + 1]);
    int cnt = e1 - e0;

    int sr = (lane < cnt) ? __ldg(&g_srow[e0 + lane]) : 0;

    float4 a0 = make_float4(0.f, 0.f, 0.f, 0.f);
    float4 a1 = make_float4(0.f, 0.f, 0.f, 0.f);
    float4 a2 = make_float4(0.f, 0.f, 0.f, 0.f);
    float4 a3 = make_float4(0.f, 0.f, 0.f, 0.f);

    int m = cnt < 32 ? cnt : 32;
    int j = 0;
    for (; j + 3 < m; j += 4) {
        int ra = __shfl_sync(0xFFFFFFFFu, sr, j);
        int rb = __shfl_sync(0xFFFFFFFFu, sr, j + 1);
        int rc = __shfl_sync(0xFFFFFFFFu, sr, j + 2);
        int rd = __shfl_sync(0xFFFFFFFFu, sr, j + 3);
        acc_row(a0, ra, lane);
        acc_row(a1, rb, lane);
        acc_row(a2, rc, lane);
        acc_row(a3, rd, lane);
    }
    for (; j < m; j++) {
        int ra = __shfl_sync(0xFFFFFFFFu, sr, j);
        acc_row(a0, ra, lane);
    }
    for (int e = e0 + 32; e < e1; e++) {   // rare deg>32 tail
        acc_row(a0, g_srow[e], lane);
    }
    a0.x += a1.x + a2.x + a3.x;
    a0.y += a1.y + a2.y + a3.y;
    a0.z += a1.z + a2.z + a3.z;
    a0.w += a1.w + a2.w + a3.w;

    float d = g_dinv[n];
    float4 wv = g_xw4[n * 32 + lane];
    float4 xv = reinterpret_cast<const float4*>(x)[n * 32 + lane];
    float4 bg = __ldg(&reinterpret_cast<const float4*>(b_gcn)[lane]);

    // agg = d*sum + d^2*wv ; h = relu(agg + bg) + x
    float h0 = fmaxf(fmaf(d, a0.x, d * d * wv.x) + bg.x, 0.f) + xv.x;
    float h1 = fmaxf(fmaf(d, a0.y, d * d * wv.y) + bg.y, 0.f) + xv.y;
    float h2 = fmaxf(fmaf(d, a0.z, d * d * wv.z) + bg.z, 0.f) + xv.z;
    float h3 = fmaxf(fmaf(d, a0.w, d * d * wv.w) + bg.w, 0.f) + xv.w;

    // layer 1: [128] -> [32]
    float s1 = __ldg(&b1[lane]);
    #pragma unroll
    for (int s = 0; s < 32; s++) {
        float t0 = __shfl_sync(0xFFFFFFFFu, h0, s);
        float t1 = __shfl_sync(0xFFFFFFFFu, h1, s);
        float t2 = __shfl_sync(0xFFFFFFFFu, h2, s);
        float t3 = __shfl_sync(0xFFFFFFFFu, h3, s);
        int k = s * 4;
        s1 = fmaf(t0, __ldg(&w1[(k + 0) * HH + lane]), s1);
        s1 = fmaf(t1, __ldg(&w1[(k + 1) * HH + lane]), s1);
        s1 = fmaf(t2, __ldg(&w1[(k + 2) * HH + lane]), s1);
        s1 = fmaf(t3, __ldg(&w1[(k + 3) * HH + lane]), s1);
    }
    s1 = fmaxf(s1, 0.f);

    // layer 2: [32] -> [32]
    float s2 = __ldg(&b2[lane]);
    #pragma unroll
    for (int s = 0; s < 32; s++) {
        float t = __shfl_sync(0xFFFFFFFFu, s1, s);
        s2 = fmaf(t, __ldg(&w2[s * HH + lane]), s2);
    }
    s2 = fmaxf(s2, 0.f);

    // layer 3: [32] -> [1]
    float p = s2 * __ldg(&w3[lane]);
    #pragma unroll
    for (int off = 16; off > 0; off >>= 1)
        p += __shfl_xor_sync(0xFFFFFFFFu, p, off);

    if (lane == 0) out[n] = p + __ldg(&b3[0]);
}

// ---------------------------------------------------------------------------
// launch — fork/join: GEMM chain on side stream overlaps CSR build
// ---------------------------------------------------------------------------
extern "C" void kernel_launch(void* const* d_in, const int* in_sizes, int n_in,
                              void* d_out, int out_size) {
    const float* x     = (const float*)d_in[0];
    const int*   ei    = (const int*)  d_in[1];
    const float* W_gcn = (const float*)d_in[2];
    const float* b_gcn = (const float*)d_in[3];
    const float* w1    = (const float*)d_in[4];
    const float* b1    = (const float*)d_in[5];
    const float* w2    = (const float*)d_in[6];
    const float* b2    = (const float*)d_in[7];
    const float* w3    = (const float*)d_in[8];
    const float* b3    = (const float*)d_in[9];
    float* out = (float*)d_out;

    const int smem_bytes = (64 * XS_STRIDE + 128 * WS_STRIDE) * sizeof(float);
    static cudaStream_t s1 = nullptr;
    static cudaEvent_t evRoot, evScan1, evScale;
    if (s1 == nullptr) {   // first (non-capture correctness) call only
        cudaFuncSetAttribute(k_gemm_mma, cudaFuncAttributeMaxDynamicSharedMemorySize,
                             smem_bytes);
        cudaStreamCreateWithFlags(&s1, cudaStreamNonBlocking);
        cudaEventCreateWithFlags(&evRoot,  cudaEventDisableTiming);
        cudaEventCreateWithFlags(&evScan1, cudaEventDisableTiming);
        cudaEventCreateWithFlags(&evScale, cudaEventDisableTiming);
    }

    const int nblk = (NN + 255) / 256;  // 196

    // fork: side stream s1 runs the GEMM while main stream builds the CSR
    cudaEventRecord(evRoot, 0);
    cudaStreamWaitEvent(s1, evRoot, 0);
    k_gemm_mma<<<(NN + 63) / 64, 128, smem_bytes, s1>>>(x, W_gcn);

    k_init0  <<<nblk, 256>>>();
    k_count  <<<(EE + 255) / 256, 256>>>(ei);
    k_scan1  <<<nblk, 256>>>();
    cudaEventRecord(evScan1, 0);              // dinv ready
    cudaStreamWaitEvent(s1, evScan1, 0);
    k_scale  <<<(NN * 32 + 255) / 256, 256, 0, s1>>>();
    cudaEventRecord(evScale, s1);

    k_scan2  <<<1, 256>>>(nblk);
    k_scan3  <<<nblk, 256>>>();
    k_scatter<<<(EE + 255) / 256, 256>>>(ei);

    // join
    cudaStreamWaitEvent(0, evScale, 0);
    k_aggmlp <<<(NN * 32 + 255) / 256, 256>>>(x, b_gcn, w1, b1, w2, b2, w3, b3, out);
}

// round 6
// speedup vs baseline: 2.2104x; 1.3143x over previous
#include <cuda_runtime.h>
#include <cuda_bf16.h>
#include <cuda_fp16.h>
#include <cstdint>

#define NN 50000
#define EE 600000
#define DD 128
#define HH 32

// ---------------------------------------------------------------------------
// Scratch
// ---------------------------------------------------------------------------
__device__ float4  g_xw4[NN * (DD / 4)];  // xw = x @ W_gcn (fp32, self term)
__device__ __half2 g_xwh2[NN * (DD / 2)]; // dinv[row]*xw[row] in fp16 (gather)
__device__ float   g_dinv[NN];
__device__ int     g_deg[NN];             // zeroed by k_aggmlp of PREVIOUS call
__device__ int     g_excl[NN];
__device__ int     g_bsum[256];
__device__ int     g_boff[256];
__device__ int     g_rowstart[NN + 1];
__device__ int     g_cursor[NN];
__device__ int     g_srow[EE];

// ---------------------------------------------------------------------------
__global__ void k_count(const int* __restrict__ ei) {
    int i = blockIdx.x * blockDim.x + threadIdx.x;
    if (i >= EE) return;
    atomicAdd(&g_deg[__ldg(&ei[EE + i])], 1);
}

__global__ __launch_bounds__(256) void k_scan1() {
    __shared__ int wsum[8];
    const int tid  = threadIdx.x;
    const int lane = tid & 31;
    const int w    = tid >> 5;
    const int i    = blockIdx.x * 256 + tid;

    int v = (i < NN) ? g_deg[i] : 0;
    int incl = v;
    #pragma unroll
    for (int d = 1; d < 32; d <<= 1) {
        int t = __shfl_up_sync(0xFFFFFFFFu, incl, d);
        if (lane >= d) incl += t;
    }
    if (lane == 31) wsum[w] = incl;
    __syncthreads();
    if (w == 0 && lane < 8) {
        int s = wsum[lane];
        #pragma unroll
        for (int d = 1; d < 8; d <<= 1) {
            int t = __shfl_up_sync(0xFFu, s, d);
            if (lane >= d) s += t;
        }
        wsum[lane] = s;
    }
    __syncthreads();
    int offs = (w > 0) ? wsum[w - 1] : 0;
    if (i < NN) {
        g_excl[i] = offs + incl - v;
        g_dinv[i] = rsqrtf((float)(v + 1));
    }
    if (tid == 255) g_bsum[blockIdx.x] = wsum[7];
}

__global__ __launch_bounds__(256) void k_scan2(int nblk) {
    __shared__ int wsum[8];
    const int tid  = threadIdx.x;
    const int lane = tid & 31;
    const int w    = tid >> 5;
    int v = (tid < nblk) ? g_bsum[tid] : 0;
    int incl = v;
    #pragma unroll
    for (int d = 1; d < 32; d <<= 1) {
        int t = __shfl_up_sync(0xFFFFFFFFu, incl, d);
        if (lane >= d) incl += t;
    }
    if (lane == 31) wsum[w] = incl;
    __syncthreads();
    if (w == 0 && lane < 8) {
        int s = wsum[lane];
        #pragma unroll
        for (int d = 1; d < 8; d <<= 1) {
            int t = __shfl_up_sync(0xFFu, s, d);
            if (lane >= d) s += t;
        }
        wsum[lane] = s;
    }
    __syncthreads();
    int offs = (w > 0) ? wsum[w - 1] : 0;
    g_boff[tid] = offs + incl - v;
}

__global__ __launch_bounds__(256) void k_scan3() {
    int i = blockIdx.x * blockDim.x + threadIdx.x;
    if (i < NN) {
        int r = g_excl[i] + g_boff[i >> 8];
        g_rowstart[i] = r;
        g_cursor[i]   = r;
    }
    if (i == 0) g_rowstart[NN] = EE;
}

__global__ void k_scatter(const int* __restrict__ ei) {
    int i = blockIdx.x * blockDim.x + threadIdx.x;
    if (i >= EE) return;
    int row = __ldg(&ei[i]);
    int col = __ldg(&ei[EE + i]);
    int pos = atomicAdd(&g_cursor[col], 1);
    g_srow[pos] = row;
}

// ---------------------------------------------------------------------------
// K4: xw = x @ W via mma.sync tf32 (validated in R4)
// ---------------------------------------------------------------------------
__device__ __forceinline__ uint32_t f2tf32(float f) {
    uint32_t r;
    asm("cvt.rna.tf32.f32 %0, %1;" : "=r"(r) : "f"(f));
    return r;
}

#define XS_STRIDE 132
#define WS_STRIDE 136

__global__ __launch_bounds__(128) void k_gemm_mma(const float* __restrict__ x,
                                                  const float* __restrict__ W) {
    extern __shared__ float smem[];
    float* xs = smem;
    float* ws = smem + 64 * XS_STRIDE;

    const int tid  = threadIdx.x;
    const int lane = tid & 31;
    const int warp = tid >> 5;
    const int row0 = blockIdx.x * 64;

    #pragma unroll
    for (int it = 0; it < 32; it++) {
        int idx = tid + it * 128;
        int k  = idx >> 5;
        int c4 = (idx & 31) * 4;
        float4 v = __ldg(reinterpret_cast<const float4*>(&W[k * DD + c4]));
        float* d = &ws[k * WS_STRIDE + c4];
        d[0] = __uint_as_float(f2tf32(v.x));
        d[1] = __uint_as_float(f2tf32(v.y));
        d[2] = __uint_as_float(f2tf32(v.z));
        d[3] = __uint_as_float(f2tf32(v.w));
    }
    #pragma unroll
    for (int it = 0; it < 16; it++) {
        int idx = tid + it * 128;
        int r  = idx >> 5;
        int c4 = (idx & 31) * 4;
        int g  = row0 + r;
        float4 v = make_float4(0.f, 0.f, 0.f, 0.f);
        if (g < NN) v = __ldg(reinterpret_cast<const float4*>(&x[g * DD + c4]));
        float* d = &xs[r * XS_STRIDE + c4];
        d[0] = __uint_as_float(f2tf32(v.x));
        d[1] = __uint_as_float(f2tf32(v.y));
        d[2] = __uint_as_float(f2tf32(v.z));
        d[3] = __uint_as_float(f2tf32(v.w));
    }
    __syncthreads();

    const int g  = lane >> 2;
    const int tg = lane & 3;
    const int wrow = warp * 16;

    float acc[16][4];
    #pragma unroll
    for (int nt = 0; nt < 16; nt++)
        #pragma unroll
        for (int q = 0; q < 4; q++) acc[nt][q] = 0.f;

    #pragma unroll
    for (int kk = 0; kk < DD; kk += 8) {
        uint32_t a0 = __float_as_uint(xs[(wrow + g    ) * XS_STRIDE + kk + tg    ]);
        uint32_t a1 = __float_as_uint(xs[(wrow + g + 8) * XS_STRIDE + kk + tg    ]);
        uint32_t a2 = __float_as_uint(xs[(wrow + g    ) * XS_STRIDE + kk + tg + 4]);
        uint32_t a3 = __float_as_uint(xs[(wrow + g + 8) * XS_STRIDE + kk + tg + 4]);
        #pragma unroll
        for (int nt = 0; nt < 16; nt++) {
            uint32_t b0 = __float_as_uint(ws[(kk + tg    ) * WS_STRIDE + nt * 8 + g]);
            uint32_t b1 = __float_as_uint(ws[(kk + tg + 4) * WS_STRIDE + nt * 8 + g]);
            asm volatile(
                "mma.sync.aligned.m16n8k8.row.col.f32.tf32.tf32.f32 "
                "{%0,%1,%2,%3}, {%4,%5,%6,%7}, {%8,%9}, {%0,%1,%2,%3};"
                : "+f"(acc[nt][0]), "+f"(acc[nt][1]), "+f"(acc[nt][2]), "+f"(acc[nt][3])
                : "r"(a0), "r"(a1), "r"(a2), "r"(a3), "r"(b0), "r"(b1));
        }
    }

    float* xw = reinterpret_cast<float*>(g_xw4);
    int r_lo = row0 + wrow + g;
    int r_hi = r_lo + 8;
    #pragma unroll
    for (int nt = 0; nt < 16; nt++) {
        int col = nt * 8 + 2 * tg;
        if (r_lo < NN) {
            float2 v = make_float2(acc[nt][0], acc[nt][1]);
            *reinterpret_cast<float2*>(&xw[r_lo * DD + col]) = v;
        }
        if (r_hi < NN) {
            float2 v = make_float2(acc[nt][2], acc[nt][3]);
            *reinterpret_cast<float2*>(&xw[r_hi * DD + col]) = v;
        }
    }
}

// ---------------------------------------------------------------------------
// K4b: xws = fp16(dinv[row] * xw[row])
// ---------------------------------------------------------------------------
__global__ __launch_bounds__(256) void k_scale() {
    int idx = blockIdx.x * blockDim.x + threadIdx.x;
    if (idx >= NN * 32) return;
    float d = g_dinv[idx >> 5];
    float4 v = g_xw4[idx];
    __half2 h0 = __floats2half2_rn(v.x * d, v.y * d);
    __half2 h1 = __floats2half2_rn(v.z * d, v.w * d);
    uint2 u;
    u.x = *reinterpret_cast<uint32_t*>(&h0);
    u.y = *reinterpret_cast<uint32_t*>(&h1);
    *reinterpret_cast<uint2*>(&g_xwh2[idx * 2]) = u;
}

// ---------------------------------------------------------------------------
// K5: block of 256 threads handles 64 nodes.
//   Phase A (8 warps, 8 nodes each): CSR gather + GCN epilogue -> h in smem (tf32)
//   Phase B (warps 0-3): MLP as tensor-core GEMMs 64x128@128x32 -> 64x32@32x32
//   Phase C (threads 0-63): 32-dot with w3 -> out
// ---------------------------------------------------------------------------
#define HS 132   // h stride (floats)
#define SS 36    // layer-out stride (floats)

__device__ __forceinline__ void acc_row(float4& a, int row, int lane) {
    uint2 u = __ldg(reinterpret_cast<const uint2*>(&g_xwh2[row * 64 + lane * 2]));
    float2 fa = __half22float2(*reinterpret_cast<__half2*>(&u.x));
    float2 fb = __half22float2(*reinterpret_cast<__half2*>(&u.y));
    a.x += fa.x; a.y += fa.y; a.z += fb.x; a.w += fb.y;
}

__global__ __launch_bounds__(256) void k_aggmlp(const float* __restrict__ x,
                                                const float* __restrict__ b_gcn,
                                                const float* __restrict__ w1,
                                                const float* __restrict__ b1,
                                                const float* __restrict__ w2,
                                                const float* __restrict__ b2,
                                                const float* __restrict__ w3,
                                                const float* __restrict__ b3,
                                                float* __restrict__ out) {
    extern __shared__ float smem[];
    float* hs  = smem;                 // [64][HS]  h, tf32 bits
    float* s1s = smem + 64 * HS;       // [64][SS]  layer1 out, tf32 bits
    float* s2s = s1s + 64 * SS;        // [64][SS]  layer2 out, fp32

    const int tid  = threadIdx.x;
    const int lane = tid & 31;
    const int warp = tid >> 5;
    const int nbase = blockIdx.x * 64;

    // zero g_deg for the NEXT kernel_launch invocation (before any sync; this
    // kernel never reads g_deg)
    if (tid < 64 && nbase + tid < NN) g_deg[nbase + tid] = 0;

    float4 bg = __ldg(&reinterpret_cast<const float4*>(b_gcn)[lane]);

    // ---- Phase A: gather + epilogue, 8 nodes per warp ----
    #pragma unroll 1
    for (int i = 0; i < 8; i++) {
        int r = warp * 8 + i;          // local row
        int n = nbase + r;
        if (n >= NN) {
            float4 z = make_float4(0.f, 0.f, 0.f, 0.f);
            *reinterpret_cast<float4*>(&hs[r * HS + lane * 4]) = z;
            continue;
        }
        int e0  = __ldg(&g_rowstart[n]);
        int e1  = __ldg(&g_rowstart[n + 1]);
        int cnt = e1 - e0;

        int sr = (lane < cnt) ? __ldg(&g_srow[e0 + lane]) : 0;

        float4 a0 = make_float4(0.f, 0.f, 0.f, 0.f);
        float4 a1 = make_float4(0.f, 0.f, 0.f, 0.f);
        float4 a2 = make_float4(0.f, 0.f, 0.f, 0.f);
        float4 a3 = make_float4(0.f, 0.f, 0.f, 0.f);

        int m = cnt < 32 ? cnt : 32;
        int j = 0;
        for (; j + 3 < m; j += 4) {
            int ra = __shfl_sync(0xFFFFFFFFu, sr, j);
            int rb = __shfl_sync(0xFFFFFFFFu, sr, j + 1);
            int rc = __shfl_sync(0xFFFFFFFFu, sr, j + 2);
            int rd = __shfl_sync(0xFFFFFFFFu, sr, j + 3);
            acc_row(a0, ra, lane);
            acc_row(a1, rb, lane);
            acc_row(a2, rc, lane);
            acc_row(a3, rd, lane);
        }
        for (; j < m; j++) {
            int ra = __shfl_sync(0xFFFFFFFFu, sr, j);
            acc_row(a0, ra, lane);
        }
        for (int e = e0 + 32; e < e1; e++) acc_row(a0, g_srow[e], lane);
        a0.x += a1.x + a2.x + a3.x;
        a0.y += a1.y + a2.y + a3.y;
        a0.z += a1.z + a2.z + a3.z;
        a0.w += a1.w + a2.w + a3.w;

        float d = g_dinv[n];
        float4 wv = g_xw4[n * 32 + lane];
        float4 xv = reinterpret_cast<const float4*>(x)[n * 32 + lane];

        float h0 = fmaxf(fmaf(d, a0.x, d * d * wv.x) + bg.x, 0.f) + xv.x;
        float h1 = fmaxf(fmaf(d, a0.y, d * d * wv.y) + bg.y, 0.f) + xv.y;
        float h2 = fmaxf(fmaf(d, a0.z, d * d * wv.z) + bg.z, 0.f) + xv.z;
        float h3 = fmaxf(fmaf(d, a0.w, d * d * wv.w) + bg.w, 0.f) + xv.w;

        float4 hv = make_float4(__uint_as_float(f2tf32(h0)),
                                __uint_as_float(f2tf32(h1)),
                                __uint_as_float(f2tf32(h2)),
                                __uint_as_float(f2tf32(h3)));
        *reinterpret_cast<float4*>(&hs[r * HS + lane * 4]) = hv;
    }
    __syncthreads();

    const int g  = lane >> 2;
    const int tg = lane & 3;

    // ---- Phase B1: layer1 [64x128]@[128x32] + b1, relu -> s1s (tf32) ----
    if (warp < 4) {
        const int m0 = warp * 16;
        float acc[4][4];
        #pragma unroll
        for (int nt = 0; nt < 4; nt++)
            #pragma unroll
            for (int q = 0; q < 4; q++) acc[nt][q] = 0.f;

        #pragma unroll
        for (int kk = 0; kk < DD; kk += 8) {
            uint32_t fa0 = __float_as_uint(hs[(m0 + g    ) * HS + kk + tg    ]);
            uint32_t fa1 = __float_as_uint(hs[(m0 + g + 8) * HS + kk + tg    ]);
            uint32_t fa2 = __float_as_uint(hs[(m0 + g    ) * HS + kk + tg + 4]);
            uint32_t fa3 = __float_as_uint(hs[(m0 + g + 8) * HS + kk + tg + 4]);
            #pragma unroll
            for (int nt = 0; nt < 4; nt++) {
                uint32_t b0 = f2tf32(__ldg(&w1[(kk + tg    ) * HH + nt * 8 + g]));
                uint32_t b1r = f2tf32(__ldg(&w1[(kk + tg + 4) * HH + nt * 8 + g]));
                asm volatile(
                    "mma.sync.aligned.m16n8k8.row.col.f32.tf32.tf32.f32 "
                    "{%0,%1,%2,%3}, {%4,%5,%6,%7}, {%8,%9}, {%0,%1,%2,%3};"
                    : "+f"(acc[nt][0]), "+f"(acc[nt][1]), "+f"(acc[nt][2]), "+f"(acc[nt][3])
                    : "r"(fa0), "r"(fa1), "r"(fa2), "r"(fa3), "r"(b0), "r"(b1r));
            }
        }
        #pragma unroll
        for (int nt = 0; nt < 4; nt++) {
            int c0 = nt * 8 + 2 * tg;
            float bb0 = __ldg(&b1[c0]);
            float bb1 = __ldg(&b1[c0 + 1]);
            s1s[(m0 + g    ) * SS + c0    ] = __uint_as_float(f2tf32(fmaxf(acc[nt][0] + bb0, 0.f)));
            s1s[(m0 + g    ) * SS + c0 + 1] = __uint_as_float(f2tf32(fmaxf(acc[nt][1] + bb1, 0.f)));
            s1s[(m0 + g + 8) * SS + c0    ] = __uint_as_float(f2tf32(fmaxf(acc[nt][2] + bb0, 0.f)));
            s1s[(m0 + g + 8) * SS + c0 + 1] = __uint_as_float(f2tf32(fmaxf(acc[nt][3] + bb1, 0.f)));
        }
    }
    __syncthreads();

    // ---- Phase B2: layer2 [64x32]@[32x32] + b2, relu -> s2s (fp32) ----
    if (warp < 4) {
        const int m0 = warp * 16;
        float acc[4][4];
        #pragma unroll
        for (int nt = 0; nt < 4; nt++)
            #pragma unroll
            for (int q = 0; q < 4; q++) acc[nt][q] = 0.f;

        #pragma unroll
        for (int kk = 0; kk < HH; kk += 8) {
            uint32_t fa0 = __float_as_uint(s1s[(m0 + g    ) * SS + kk + tg    ]);
            uint32_t fa1 = __float_as_uint(s1s[(m0 + g + 8) * SS + kk + tg    ]);
            uint32_t fa2 = __float_as_uint(s1s[(m0 + g    ) * SS + kk + tg + 4]);
            uint32_t fa3 = __float_as_uint(s1s[(m0 + g + 8) * SS + kk + tg + 4]);
            #pragma unroll
            for (int nt = 0; nt < 4; nt++) {
                uint32_t b0 = f2tf32(__ldg(&w2[(kk + tg    ) * HH + nt * 8 + g]));
                uint32_t b1r = f2tf32(__ldg(&w2[(kk + tg + 4) * HH + nt * 8 + g]));
                asm volatile(
                    "mma.sync.aligned.m16n8k8.row.col.f32.tf32.tf32.f32 "
                    "{%0,%1,%2,%3}, {%4,%5,%6,%7}, {%8,%9}, {%0,%1,%2,%3};"
                    : "+f"(acc[nt][0]), "+f"(acc[nt][1]), "+f"(acc[nt][2]), "+f"(acc[nt][3])
                    : "r"(fa0), "r"(fa1), "r"(fa2), "r"(fa3), "r"(b0), "r"(b1r));
            }
        }
        #pragma unroll
        for (int nt = 0; nt < 4; nt++) {
            int c0 = nt * 8 + 2 * tg;
            float bb0 = __ldg(&b2[c0]);
            float bb1 = __ldg(&b2[c0 + 1]);
            s2s[(m0 + g    ) * SS + c0    ] = fmaxf(acc[nt][0] + bb0, 0.f);
            s2s[(m0 + g    ) * SS + c0 + 1] = fmaxf(acc[nt][1] + bb1, 0.f);
            s2s[(m0 + g + 8) * SS + c0    ] = fmaxf(acc[nt][2] + bb0, 0.f);
            s2s[(m0 + g + 8) * SS + c0 + 1] = fmaxf(acc[nt][3] + bb1, 0.f);
        }
    }
    __syncthreads();

    // ---- Phase C: layer3 [64x32]@[32x1] + b3 ----
    if (tid < 64) {
        int n = nbase + tid;
        if (n < NN) {
            float p = 0.f;
            #pragma unroll
            for (int j = 0; j < HH; j++)
                p = fmaf(s2s[tid * SS + j], __ldg(&w3[j]), p);
            out[n] = p + __ldg(&b3[0]);
        }
    }
}

// ---------------------------------------------------------------------------
// launch — fork/join: GEMM chain on side stream overlaps CSR build
// ---------------------------------------------------------------------------
extern "C" void kernel_launch(void* const* d_in, const int* in_sizes, int n_in,
                              void* d_out, int out_size) {
    const float* x     = (const float*)d_in[0];
    const int*   ei    = (const int*)  d_in[1];
    const float* W_gcn = (const float*)d_in[2];
    const float* b_gcn = (const float*)d_in[3];
    const float* w1    = (const float*)d_in[4];
    const float* b1    = (const float*)d_in[5];
    const float* w2    = (const float*)d_in[6];
    const float* b2    = (const float*)d_in[7];
    const float* w3    = (const float*)d_in[8];
    const float* b3    = (const float*)d_in[9];
    float* out = (float*)d_out;

    const int smem_gemm = (64 * XS_STRIDE + 128 * WS_STRIDE) * sizeof(float);
    const int smem_agg  = (64 * HS + 64 * SS + 64 * SS) * sizeof(float);
    static cudaStream_t s1 = nullptr;
    static cudaEvent_t evRoot, evScan1, evScale;
    if (s1 == nullptr) {   // first (non-capture correctness) call only
        cudaFuncSetAttribute(k_gemm_mma, cudaFuncAttributeMaxDynamicSharedMemorySize,
                             smem_gemm);
        cudaFuncSetAttribute(k_aggmlp, cudaFuncAttributeMaxDynamicSharedMemorySize,
                             smem_agg);
        cudaStreamCreateWithFlags(&s1, cudaStreamNonBlocking);
        cudaEventCreateWithFlags(&evRoot,  cudaEventDisableTiming);
        cudaEventCreateWithFlags(&evScan1, cudaEventDisableTiming);
        cudaEventCreateWithFlags(&evScale, cudaEventDisableTiming);
    }

    const int nblk = (NN + 255) / 256;  // 196

    // fork: side stream s1 runs the GEMM while main stream builds the CSR
    cudaEventRecord(evRoot, 0);
    cudaStreamWaitEvent(s1, evRoot, 0);
    k_gemm_mma<<<(NN + 63) / 64, 128, smem_gemm, s1>>>(x, W_gcn);

    k_count  <<<(EE + 255) / 256, 256>>>(ei);
    k_scan1  <<<nblk, 256>>>();
    cudaEventRecord(evScan1, 0);              // dinv ready
    cudaStreamWaitEvent(s1, evScan1, 0);
    k_scale  <<<(NN * 32 + 255) / 256, 256, 0, s1>>>();
    cudaEventRecord(evScale, s1);

    k_scan2  <<<1, 256>>>(nblk);
    k_scan3  <<<nblk, 256>>>();
    k_scatter<<<(EE + 255) / 256, 256>>>(ei);

    // join
    cudaStreamWaitEvent(0, evScale, 0);
    k_aggmlp <<<(NN + 63) / 64, 256, smem_agg>>>(x, b_gcn, w1, b1, w2, b2, w3, b3, out);
}